// round 8
// baseline (speedup 1.0000x reference)
#include <cuda_runtime.h>
#include <cstdint>

#define SQ 2048
#define NB 16
#define HD 64
#define MASKW (SQ*SQ/32)        /* 131,072 words = 512 KB */
#define NELEM (NB*SQ*HD)        /* 2,097,152 per tensor */

__device__ uint32_t g_mbits[MASKW];
__device__ float g_q[NELEM];    /* pre-scaled (1/8) + tf32-rounded */
__device__ float g_k[NELEM];    /* tf32-rounded */
__device__ float g_v[NELEM];    /* tf32-rounded */

__device__ __forceinline__ uint32_t cvt_tf32(float x) {
    uint32_t u; asm("cvt.rna.tf32.f32 %0, %1;" : "=r"(u) : "f"(x)); return u;
}

// threefry2x32 partitionable, key=(0,42): keep decision for counter i
// (bits>>9) < 7549747  <=>  bits < 7549747*512 = 0xE6666600
__device__ __forceinline__ bool tf_keep(uint32_t i) {
    const uint32_t ks1 = 42u;
    const uint32_t ks2 = 0x1BD11BDAu ^ 42u;
    uint32_t x0 = 0u, x1 = i + ks1;
#define TFR(r) { x0 += x1; x1 = __funnelshift_l(x1, x1, r); x1 ^= x0; }
    TFR(13) TFR(15) TFR(26) TFR(6)
    x0 += ks1; x1 += ks2 + 1u;
    TFR(17) TFR(29) TFR(16) TFR(24)
    x0 += ks2; x1 += 2u;
    TFR(13) TFR(15) TFR(26) TFR(6)
    x1 += ks1 + 3u;
    TFR(17) TFR(29) TFR(16) TFR(24)
    x0 += ks1; x1 += ks2 + 4u;
    TFR(13) TFR(15) TFR(26) TFR(6)
    x0 += ks2; x1 += 5u;
#undef TFR
    return (x0 ^ x1) < 0xE6666600u;
}

// ===========================================================================
// pre-round Q (scaled), K, V to tf32 values stored as fp32
// ===========================================================================
__global__ void round_kernel(const float4* __restrict__ q,
                             const float4* __restrict__ k,
                             const float4* __restrict__ v) {
    int i = blockIdx.x * blockDim.x + threadIdx.x;
    float4 t = __ldg(q + i);
    float4 u;
    u.x = __uint_as_float(cvt_tf32(t.x * 0.125f));
    u.y = __uint_as_float(cvt_tf32(t.y * 0.125f));
    u.z = __uint_as_float(cvt_tf32(t.z * 0.125f));
    u.w = __uint_as_float(cvt_tf32(t.w * 0.125f));
    ((float4*)g_q)[i] = u;
    t = __ldg(k + i);
    u.x = __uint_as_float(cvt_tf32(t.x));
    u.y = __uint_as_float(cvt_tf32(t.y));
    u.z = __uint_as_float(cvt_tf32(t.z));
    u.w = __uint_as_float(cvt_tf32(t.w));
    ((float4*)g_k)[i] = u;
    t = __ldg(v + i);
    u.x = __uint_as_float(cvt_tf32(t.x));
    u.y = __uint_as_float(cvt_tf32(t.y));
    u.z = __uint_as_float(cvt_tf32(t.z));
    u.w = __uint_as_float(cvt_tf32(t.w));
    ((float4*)g_v)[i] = u;
}

// ===========================================================================
// pack attn_mask into bits (bit=1 -> unmasked)
// ===========================================================================
__global__ void pack_mask_kernel(const int* __restrict__ mask) {
    uint32_t lane = threadIdx.x & 31u;
    uint32_t warp = (blockIdx.x * blockDim.x + threadIdx.x) >> 5;
    uint32_t nw   = (gridDim.x * blockDim.x) >> 5;
    for (uint32_t w = warp * 4u; w < MASKW; w += nw * 4u) {
        int v0 = __ldg(mask + (size_t)w * 32 + lane);
        int v1 = __ldg(mask + (size_t)(w + 1) * 32 + lane);
        int v2 = __ldg(mask + (size_t)(w + 2) * 32 + lane);
        int v3 = __ldg(mask + (size_t)(w + 3) * 32 + lane);
        uint4 b;
        b.x = __ballot_sync(0xffffffffu, v0 != 0);
        b.y = __ballot_sync(0xffffffffu, v1 != 0);
        b.z = __ballot_sync(0xffffffffu, v2 != 0);
        b.w = __ballot_sync(0xffffffffu, v3 != 0);
        if (lane == 0) *(uint4*)(g_mbits + w) = b;
    }
}

// ===========================================================================
// fused tf32 mma.sync flash attention + inline threefry dropout
// CTA: 256 threads = 8 warps x 16 q-rows = 128 rows. 256 CTAs, 2/SM
// -> 16 warps/SM for cross-warp pipe mixing (alu threefry vs tensor/mufu).
// Key tile 64, cp.async double-buffered, shuffle refragmentation (no P smem).
// ===========================================================================

#define KPITCH 68
#define VPITCH 72
#define KBUF (64*KPITCH)                 /* 4352 floats */
#define VBUF (64*VPITCH)                 /* 4608 floats */
#define BUFSZ (KBUF+VBUF)                /* 8960 floats per stage buffer */
#define SMEM_BYTES (2*BUFSZ*4)           /* 71,680 B -> 2 CTAs/SM */

#define CP16(dst, src) asm volatile("cp.async.cg.shared.global [%0], [%1], 16;" :: "r"(dst), "l"(src) : "memory")
#define CP_COMMIT()    asm volatile("cp.async.commit_group;" ::: "memory")
#define CP_WAIT0()     asm volatile("cp.async.wait_group 0;" ::: "memory")

__device__ __forceinline__ uint32_t s2u(const void* p) {
    uint32_t a;
    asm("{ .reg .u64 t; cvta.to.shared.u64 t, %1; cvt.u32.u64 %0, t; }" : "=r"(a) : "l"(p));
    return a;
}

__device__ __forceinline__ void mma_tf32(float c[4], const uint32_t a[4],
                                         uint32_t b0, uint32_t b1) {
    asm volatile(
        "mma.sync.aligned.m16n8k8.row.col.f32.tf32.tf32.f32 "
        "{%0,%1,%2,%3}, {%4,%5,%6,%7}, {%8,%9}, {%0,%1,%2,%3};"
        : "+f"(c[0]), "+f"(c[1]), "+f"(c[2]), "+f"(c[3])
        : "r"(a[0]), "r"(a[1]), "r"(a[2]), "r"(a[3]), "r"(b0), "r"(b1));
}

__global__ void __launch_bounds__(256, 2) flash_mma_kernel(float* __restrict__ out)
{
    extern __shared__ float sm[];
    const uint32_t sb = s2u(sm);

    const int tid  = threadIdx.x;
    const int wid  = tid >> 5;                    // 0..7
    const int lane = tid & 31;
    const int g    = lane >> 2;
    const int e    = lane & 3;
    const int b    = blockIdx.x >> 4;
    const int qt   = blockIdx.x & 15;
    const int qbw  = qt * 128 + wid * 16;         // warp's q-row base
    const float INVK = (float)(1.0 / 0.9);

    // staging role: 4 threads per row, 64 rows, 16 floats each
    const int srow = tid >> 2;
    const int shf  = tid & 3;
    const float* ksrc = g_k + ((size_t)(b * SQ + srow)) * HD + shf * 16;
    const float* vsrc = g_v + ((size_t)(b * SQ + srow)) * HD + shf * 16;
    const uint32_t kdst = sb + (uint32_t)((srow * KPITCH + shf * 16) * 4);
    const uint32_t vdst = sb + (uint32_t)((KBUF + srow * VPITCH + shf * 16) * 4);

    // ---- Q fragments (16 rows/warp), persistent ----
    uint32_t qa[8][4];
    {
        const float* q0 = g_q + ((size_t)(b * SQ + qbw + g)) * HD + e;
        const float* q1 = q0 + 8 * HD;
#pragma unroll
        for (int kf = 0; kf < 8; kf++) {
            qa[kf][0] = __float_as_uint(__ldg(q0 + kf * 8));
            qa[kf][1] = __float_as_uint(__ldg(q1 + kf * 8));
            qa[kf][2] = __float_as_uint(__ldg(q0 + kf * 8 + 4));
            qa[kf][3] = __float_as_uint(__ldg(q1 + kf * 8 + 4));
        }
    }

    float dpv[8][4];
#pragma unroll
    for (int nf = 0; nf < 8; nf++)
#pragma unroll
        for (int j = 0; j < 4; j++) dpv[nf][j] = 0.0f;
    float l0 = 0.0f, l1 = 0.0f;

    // threefry counter bases for my two rows (col term 2e folded in)
    const uint32_t ctr0 = ((uint32_t)(b * SQ + qbw + g) << 11) + 2u * (uint32_t)e;
    const uint32_t ctr1 = ctr0 + (8u << 11);
    const uint32_t* mb0 = g_mbits + (size_t)(qbw + g) * (SQ / 32);
    const uint32_t* mb1 = mb0 + 8 * (SQ / 32);

    const int src  = (lane & ~3) | (e >> 1);      // shfl source lanes (in-quad)
    const int src2 = src + 2;
    const bool eodd = (e & 1);

    // ---- prologue: stage tile 0 into buffer 0 ----
#pragma unroll
    for (int c = 0; c < 4; c++) {
        CP16(kdst + c * 16, ksrc + c * 4);
        CP16(vdst + c * 16, vsrc + c * 4);
    }
    CP_COMMIT(); CP_WAIT0();
    __syncthreads();

    for (int it = 0; it < 32; it++) {
        const int cur = it & 1;
        float* Ks = sm + cur * BUFSZ;
        float* Vs = Ks + KBUF;

        // ---- stage next tile ----
        if (it < 31) {
            const uint32_t boff = (uint32_t)((cur ^ 1) * BUFSZ * 4);
            const float* kn = ksrc + (size_t)(it + 1) * 64 * HD;
            const float* vn = vsrc + (size_t)(it + 1) * 64 * HD;
#pragma unroll
            for (int c = 0; c < 4; c++) {
                CP16(kdst + boff + c * 16, kn + c * 4);
                CP16(vdst + boff + c * 16, vn + c * 4);
            }
            CP_COMMIT();
        }

        const uint2 mw0 = *(const uint2*)(mb0 + it * 2);
        const uint2 mw1 = *(const uint2*)(mb1 + it * 2);
        const uint32_t cbase = (uint32_t)(it * 64);

#pragma unroll
        for (int nf = 0; nf < 8; nf++) {
            // ---- S block [16 x 8] = Q . K^T ----
            float c[4] = {0.f, 0.f, 0.f, 0.f};
#pragma unroll
            for (int kf = 0; kf < 8; kf++) {
                const float* kr = Ks + (nf * 8 + g) * KPITCH + kf * 8 + e;
                mma_tf32(c, qa[kf], __float_as_uint(kr[0]), __float_as_uint(kr[4]));
            }

            // ---- inline threefry keep bits (2 rows x 2 cols) ----
            const uint32_t cc = cbase + (uint32_t)(nf * 8);
            const bool k00 = tf_keep(ctr0 + cc);
            const bool k01 = tf_keep(ctr0 + cc + 1);
            const bool k10 = tf_keep(ctr1 + cc);
            const bool k11 = tf_keep(ctr1 + cc + 1);

            // ---- epilogue: mask -> exp -> l -> dropout -> tf32 ----
            const uint32_t m0 = (nf < 4) ? mw0.x : mw0.y;
            const uint32_t m1 = (nf < 4) ? mw1.x : mw1.y;
            const int bit = (nf & 3) * 8 + 2 * e;
            float p0 = ((m0 >> bit) & 1u)       ? __expf(c[0]) : 0.0f;
            float p1 = ((m0 >> (bit + 1)) & 1u) ? __expf(c[1]) : 0.0f;
            float p2 = ((m1 >> bit) & 1u)       ? __expf(c[2]) : 0.0f;
            float p3 = ((m1 >> (bit + 1)) & 1u) ? __expf(c[3]) : 0.0f;
            l0 += p0 + p1;
            l1 += p2 + p3;
            uint32_t u0 = cvt_tf32(k00 ? p0 * INVK : 0.0f);
            uint32_t u1 = cvt_tf32(k01 ? p1 * INVK : 0.0f);
            uint32_t u2 = cvt_tf32(k10 ? p2 * INVK : 0.0f);
            uint32_t u3 = cvt_tf32(k11 ? p3 * INVK : 0.0f);

            // ---- refragment D(m16n8) -> A(m16n8k8) via intra-quad shuffles ----
            uint32_t a[4];
            {
                uint32_t t0 = __shfl_sync(0xffffffffu, u0, src);
                uint32_t t1 = __shfl_sync(0xffffffffu, u1, src);
                a[0] = eodd ? t1 : t0;
                uint32_t t2 = __shfl_sync(0xffffffffu, u2, src);
                uint32_t t3 = __shfl_sync(0xffffffffu, u3, src);
                a[1] = eodd ? t3 : t2;
                uint32_t t4 = __shfl_sync(0xffffffffu, u0, src2);
                uint32_t t5 = __shfl_sync(0xffffffffu, u1, src2);
                a[2] = eodd ? t5 : t4;
                uint32_t t6 = __shfl_sync(0xffffffffu, u2, src2);
                uint32_t t7 = __shfl_sync(0xffffffffu, u3, src2);
                a[3] = eodd ? t7 : t6;
            }

            // ---- D_pv += P_block . V[kb=nf] ----
#pragma unroll
            for (int nf2 = 0; nf2 < 8; nf2++) {
                const float* vr = Vs + (nf * 8 + e) * VPITCH + nf2 * 8 + g;
                mma_tf32(dpv[nf2], a, __float_as_uint(vr[0]),
                         __float_as_uint(vr[4 * VPITCH]));
            }
        }

        if (it < 31) CP_WAIT0();
        __syncthreads();
    }

    // ---- reduce l across quad, normalize, store ----
    l0 += __shfl_xor_sync(0xffffffffu, l0, 1);
    l0 += __shfl_xor_sync(0xffffffffu, l0, 2);
    l1 += __shfl_xor_sync(0xffffffffu, l1, 1);
    l1 += __shfl_xor_sync(0xffffffffu, l1, 2);
    const float inv0 = 1.0f / l0;
    const float inv1 = 1.0f / l1;

    float* op0 = out + ((size_t)(b * SQ + qbw + g)) * HD + 2 * e;
    float* op1 = op0 + 8 * HD;
#pragma unroll
    for (int nf2 = 0; nf2 < 8; nf2++) {
        float2 t;
        t.x = dpv[nf2][0] * inv0;
        t.y = dpv[nf2][1] * inv0;
        *(float2*)(op0 + nf2 * 8) = t;
        t.x = dpv[nf2][2] * inv1;
        t.y = dpv[nf2][3] * inv1;
        *(float2*)(op1 + nf2 * 8) = t;
    }
}

// ===========================================================================
extern "C" void kernel_launch(void* const* d_in, const int* in_sizes, int n_in,
                              void* d_out, int out_size) {
    const float4* q = (const float4*)d_in[0];
    const float4* k = (const float4*)d_in[1];
    const float4* v = (const float4*)d_in[2];
    const int* mask = (const int*)d_in[3];
    float* out = (float*)d_out;

    cudaFuncSetAttribute(flash_mma_kernel,
                         cudaFuncAttributeMaxDynamicSharedMemorySize, SMEM_BYTES);

    round_kernel<<<NELEM / 4 / 256, 256>>>(q, k, v);
    pack_mask_kernel<<<1024, 256>>>(mask);
    flash_mma_kernel<<<NB * (SQ / 128), 256, SMEM_BYTES>>>(out);
}

// round 9
// speedup vs baseline: 1.0028x; 1.0028x over previous
#include <cuda_runtime.h>
#include <cstdint>

#define SQ 2048
#define NB 16
#define HD 64
#define MASKW (SQ*SQ/32)        /* 131,072 words = 512 KB */
#define NELEM (NB*SQ*HD)        /* 2,097,152 per tensor */

__device__ uint32_t g_mbits[MASKW];
__device__ float g_q[NELEM];    /* pre-scaled (1/8) + tf32-rounded */
__device__ float g_k[NELEM];    /* tf32-rounded */
__device__ float g_v[NELEM];    /* tf32-rounded */

__device__ __forceinline__ uint32_t cvt_tf32(float x) {
    uint32_t u; asm("cvt.rna.tf32.f32 %0, %1;" : "=r"(u) : "f"(x)); return u;
}

// threefry2x32 partitionable, key=(0,42): keep decision for counter i.
// (bits>>9) < 7549747  <=>  bits < 0xE6666600
// Rotates alternate SHF (alu pipe) and exact IMAD-pair (fma pipe) to balance pipes.
__device__ __forceinline__ bool tf_keep(uint32_t i) {
    const uint32_t ks1 = 42u;
    const uint32_t ks2 = 0x1BD11BDAu ^ 42u;
    uint32_t x0 = 0u, x1 = i + ks1;
#define TFRS(r) { x0 += x1; x1 = __funnelshift_l(x1, x1, r); x1 ^= x0; }
#define TFRM(r) { x0 += x1; x1 = ((x1 * (1u << r)) | __umulhi(x1, 1u << r)) ^ x0; }
    TFRM(13) TFRS(15) TFRM(26) TFRS(6)
    x0 += ks1; x1 += ks2 + 1u;
    TFRM(17) TFRS(29) TFRM(16) TFRS(24)
    x0 += ks2; x1 += 2u;
    TFRM(13) TFRS(15) TFRM(26) TFRS(6)
    x1 += ks1 + 3u;
    TFRM(17) TFRS(29) TFRM(16) TFRS(24)
    x0 += ks1; x1 += ks2 + 4u;
    TFRM(13) TFRS(15) TFRM(26) TFRS(6)
    x0 += ks2; x1 += 5u;
#undef TFRS
#undef TFRM
    return (x0 ^ x1) < 0xE6666600u;
}

// ===========================================================================
// pre-round Q (scaled), K, V to tf32 values stored as fp32
// ===========================================================================
__global__ void round_kernel(const float4* __restrict__ q,
                             const float4* __restrict__ k,
                             const float4* __restrict__ v) {
    int i = blockIdx.x * blockDim.x + threadIdx.x;
    float4 t = __ldg(q + i);
    float4 u;
    u.x = __uint_as_float(cvt_tf32(t.x * 0.125f));
    u.y = __uint_as_float(cvt_tf32(t.y * 0.125f));
    u.z = __uint_as_float(cvt_tf32(t.z * 0.125f));
    u.w = __uint_as_float(cvt_tf32(t.w * 0.125f));
    ((float4*)g_q)[i] = u;
    t = __ldg(k + i);
    u.x = __uint_as_float(cvt_tf32(t.x));
    u.y = __uint_as_float(cvt_tf32(t.y));
    u.z = __uint_as_float(cvt_tf32(t.z));
    u.w = __uint_as_float(cvt_tf32(t.w));
    ((float4*)g_k)[i] = u;
    t = __ldg(v + i);
    u.x = __uint_as_float(cvt_tf32(t.x));
    u.y = __uint_as_float(cvt_tf32(t.y));
    u.z = __uint_as_float(cvt_tf32(t.z));
    u.w = __uint_as_float(cvt_tf32(t.w));
    ((float4*)g_v)[i] = u;
}

// ===========================================================================
// pack attn_mask into bits (bit=1 -> unmasked)
// ===========================================================================
__global__ void pack_mask_kernel(const int* __restrict__ mask) {
    uint32_t lane = threadIdx.x & 31u;
    uint32_t warp = (blockIdx.x * blockDim.x + threadIdx.x) >> 5;
    uint32_t nw   = (gridDim.x * blockDim.x) >> 5;
    for (uint32_t w = warp * 4u; w < MASKW; w += nw * 4u) {
        int v0 = __ldg(mask + (size_t)w * 32 + lane);
        int v1 = __ldg(mask + (size_t)(w + 1) * 32 + lane);
        int v2 = __ldg(mask + (size_t)(w + 2) * 32 + lane);
        int v3 = __ldg(mask + (size_t)(w + 3) * 32 + lane);
        uint4 b;
        b.x = __ballot_sync(0xffffffffu, v0 != 0);
        b.y = __ballot_sync(0xffffffffu, v1 != 0);
        b.z = __ballot_sync(0xffffffffu, v2 != 0);
        b.w = __ballot_sync(0xffffffffu, v3 != 0);
        if (lane == 0) *(uint4*)(g_mbits + w) = b;
    }
}

// ===========================================================================
// Warp-specialized fused flash attention.
// 256 threads, 1 CTA/SM: warps 0-3 = consumers (tf32 mma flash, 32 q-rows
// each), warps 4-7 = producers (threefry keep bits, one per SMSP saturating
// the alu pipe). Producers generate tile it+1's keep bits into smem while
// consumers process tile it. K/V cp.async double-buffered.
// ===========================================================================

#define KPITCH 68
#define VPITCH 72
#define KBUF (64*KPITCH)                 /* 4352 floats */
#define VBUF (64*VPITCH)                 /* 4608 floats */
#define BUFSZ (KBUF+VBUF)                /* 8960 floats */
#define PS_OFF (2*BUFSZ)                 /* 17920 */
#define KB_OFF (PS_OFF + 4*32*KPITCH)    /* 26624 floats */
#define SMEM_FLOATS (KB_OFF + 2*256)     /* + 2 tiles x 256 keep words */
#define SMEM_BYTES (SMEM_FLOATS*4)       /* 108,544 B */

#define CP16(dst, src) asm volatile("cp.async.cg.shared.global [%0], [%1], 16;" :: "r"(dst), "l"(src) : "memory")
#define CP_COMMIT()    asm volatile("cp.async.commit_group;" ::: "memory")
#define CP_WAIT0()     asm volatile("cp.async.wait_group 0;" ::: "memory")

__device__ __forceinline__ uint32_t s2u(const void* p) {
    uint32_t a;
    asm("{ .reg .u64 t; cvta.to.shared.u64 t, %1; cvt.u32.u64 %0, t; }" : "=r"(a) : "l"(p));
    return a;
}

__device__ __forceinline__ void mma_tf32(float c[4], const uint32_t a[4],
                                         uint32_t b0, uint32_t b1) {
    asm volatile(
        "mma.sync.aligned.m16n8k8.row.col.f32.tf32.tf32.f32 "
        "{%0,%1,%2,%3}, {%4,%5,%6,%7}, {%8,%9}, {%0,%1,%2,%3};"
        : "+f"(c[0]), "+f"(c[1]), "+f"(c[2]), "+f"(c[3])
        : "r"(a[0]), "r"(a[1]), "r"(a[2]), "r"(a[3]), "r"(b0), "r"(b1));
}

__global__ void __launch_bounds__(256) flash_fused_kernel(float* __restrict__ out)
{
    extern __shared__ float sm[];
    const uint32_t sb = s2u(sm);
    uint32_t* kb = (uint32_t*)(sm + KB_OFF);       // [2][128][2] keep words

    const int tid  = threadIdx.x;
    const int wid  = tid >> 5;
    const int lane = tid & 31;
    const int b    = blockIdx.x >> 4;
    const int qt   = blockIdx.x & 15;
    const float INVK = (float)(1.0 / 0.9);

    if (wid >= 4) {
        // ================= PRODUCER: threefry keep bits =================
        const int pw = wid - 4;                            // 0..3, one per SMSP
        const uint32_t rowbase = (uint32_t)(b * SQ + qt * 128);

        // tile 0 into kb buffer 0
        {
            uint32_t* dst = kb;
#pragma unroll 4
            for (int j = 0; j < 64; j++) {
                const int w = (pw << 6) + j;               // 0..255
                const int row = w >> 1, cw = w & 1;
                uint32_t ctr = ((rowbase + (uint32_t)row) << 11)
                             | (uint32_t)(cw * 32 + lane);
                uint32_t bits = __ballot_sync(0xffffffffu, tf_keep(ctr));
                if (lane == 0) dst[row * 2 + cw] = bits;
            }
        }
        __syncthreads();                                   // joins consumer prologue

        for (int it = 0; it < 32; it++) {
            if (it < 31) {
                uint32_t* dst = kb + ((it + 1) & 1) * 256;
                const uint32_t cbase = (uint32_t)((it + 1) * 64);
#pragma unroll 4
                for (int j = 0; j < 64; j++) {
                    const int w = (pw << 6) + j;
                    const int row = w >> 1, cw = w & 1;
                    uint32_t ctr = ((rowbase + (uint32_t)row) << 11)
                                 | (cbase + (uint32_t)(cw * 32 + lane));
                    uint32_t bits = __ballot_sync(0xffffffffu, tf_keep(ctr));
                    if (lane == 0) dst[row * 2 + cw] = bits;
                }
            }
            __syncthreads();
        }
        return;
    }

    // ==================== CONSUMER: tf32 mma flash ====================
    const int g = lane >> 2;
    const int e = lane & 3;
    const int qbw = qt * 128 + wid * 32;                  // warp's q-row base
    float* Ps = sm + PS_OFF + wid * (32 * KPITCH);

    // staging role: consumer tids 0..127, 2 threads per row
    const int srow = tid >> 1;
    const int shf  = tid & 1;
    const float* ksrc = g_k + ((size_t)(b * SQ + srow)) * HD + shf * 32;
    const float* vsrc = g_v + ((size_t)(b * SQ + srow)) * HD + shf * 32;
    const uint32_t kdst = sb + (uint32_t)((srow * KPITCH + shf * 32) * 4);
    const uint32_t vdst = sb + (uint32_t)((KBUF + srow * VPITCH + shf * 32) * 4);

    // Q fragments (32 rows/warp = 2 m-frags), persistent
    uint32_t qa[2][8][4];
#pragma unroll
    for (int mf = 0; mf < 2; mf++) {
        const float* q0 = g_q + ((size_t)(b * SQ + qbw + mf * 16 + g)) * HD + e;
        const float* q1 = q0 + 8 * HD;
#pragma unroll
        for (int kf = 0; kf < 8; kf++) {
            qa[mf][kf][0] = __float_as_uint(__ldg(q0 + kf * 8));
            qa[mf][kf][1] = __float_as_uint(__ldg(q1 + kf * 8));
            qa[mf][kf][2] = __float_as_uint(__ldg(q0 + kf * 8 + 4));
            qa[mf][kf][3] = __float_as_uint(__ldg(q1 + kf * 8 + 4));
        }
    }

    float dpv[2][8][4];
#pragma unroll
    for (int mf = 0; mf < 2; mf++)
#pragma unroll
        for (int nf = 0; nf < 8; nf++)
#pragma unroll
            for (int j = 0; j < 4; j++) dpv[mf][nf][j] = 0.0f;
    float l[4] = {0.f, 0.f, 0.f, 0.f};

    // stage tile 0
#pragma unroll
    for (int c = 0; c < 8; c++) {
        CP16(kdst + c * 16, ksrc + c * 4);
        CP16(vdst + c * 16, vsrc + c * 4);
    }
    CP_COMMIT(); CP_WAIT0();
    __syncthreads();

    for (int it = 0; it < 32; it++) {
        const int cur = it & 1;
        float* Ks = sm + cur * BUFSZ;
        float* Vs = Ks + KBUF;

        if (it < 31) {
            const uint32_t boff = (uint32_t)((cur ^ 1) * BUFSZ * 4);
            const float* kn = ksrc + (size_t)(it + 1) * 64 * HD;
            const float* vn = vsrc + (size_t)(it + 1) * 64 * HD;
#pragma unroll
            for (int c = 0; c < 8; c++) {
                CP16(kdst + boff + c * 16, kn + c * 4);
                CP16(vdst + boff + c * 16, vn + c * 4);
            }
            CP_COMMIT();
        }

        // mask (gmem, L2) + keep (smem, from producers) words for my 4 rows
        uint2 mwv[4], kwv[4];
        const uint32_t* kcur = kb + cur * 256;
#pragma unroll
        for (int r = 0; r < 4; r++) {
            int lrow = wid * 32 + (r >> 1) * 16 + (r & 1) * 8 + g;   // 0..127
            mwv[r] = *(const uint2*)(g_mbits + (size_t)(qt * 128 + lrow) * (SQ / 32) + it * 2);
            kwv[r] = *(const uint2*)(kcur + lrow * 2);
        }

        // ---- S = QK^T (nf pairs) + epilogue -> Ps ----
#pragma unroll
        for (int np = 0; np < 4; np++) {
            float c[2][2][4];
#pragma unroll
            for (int s = 0; s < 2; s++)
#pragma unroll
                for (int mf = 0; mf < 2; mf++)
#pragma unroll
                    for (int j = 0; j < 4; j++) c[s][mf][j] = 0.0f;
#pragma unroll
            for (int kf = 0; kf < 8; kf++) {
                const float* kr0 = Ks + ((np * 2 + 0) * 8 + g) * KPITCH + kf * 8 + e;
                const float* kr1 = Ks + ((np * 2 + 1) * 8 + g) * KPITCH + kf * 8 + e;
                uint32_t b00 = __float_as_uint(kr0[0]);
                uint32_t b01 = __float_as_uint(kr0[4]);
                uint32_t b10 = __float_as_uint(kr1[0]);
                uint32_t b11 = __float_as_uint(kr1[4]);
                mma_tf32(c[0][0], qa[0][kf], b00, b01);
                mma_tf32(c[0][1], qa[1][kf], b00, b01);
                mma_tf32(c[1][0], qa[0][kf], b10, b11);
                mma_tf32(c[1][1], qa[1][kf], b10, b11);
            }
#pragma unroll
            for (int s = 0; s < 2; s++) {
                const int nf = np * 2 + s;
                const int bit = (nf & 3) * 8 + 2 * e;
#pragma unroll
                for (int mf = 0; mf < 2; mf++) {
#pragma unroll
                    for (int hf = 0; hf < 2; hf++) {
                        const int r = mf * 2 + hf;
                        uint32_t mword = (nf < 4) ? mwv[r].x : mwv[r].y;
                        uint32_t kword = (nf < 4) ? kwv[r].x : kwv[r].y;
                        float s0 = c[s][mf][hf * 2 + 0];
                        float s1 = c[s][mf][hf * 2 + 1];
                        float p0 = ((mword >> bit) & 1u) ? __expf(s0) : 0.0f;
                        float p1 = ((mword >> (bit + 1)) & 1u) ? __expf(s1) : 0.0f;
                        l[r] += p0 + p1;
                        float d0 = ((kword >> bit) & 1u) ? p0 * INVK : 0.0f;
                        float d1 = ((kword >> (bit + 1)) & 1u) ? p1 * INVK : 0.0f;
                        float2 st;
                        st.x = __uint_as_float(cvt_tf32(d0));
                        st.y = __uint_as_float(cvt_tf32(d1));
                        *(float2*)(Ps + (mf * 16 + hf * 8 + g) * KPITCH + nf * 8 + 2 * e) = st;
                    }
                }
            }
        }
        __syncwarp();

        // ---- D_pv += P . V ----
#pragma unroll
        for (int kf = 0; kf < 8; kf++) {
            uint32_t pa0[4], pa1[4];
            const float* p0 = Ps + g * KPITCH + kf * 8 + e;
            pa0[0] = __float_as_uint(p0[0]);
            pa0[1] = __float_as_uint(p0[8 * KPITCH]);
            pa0[2] = __float_as_uint(p0[4]);
            pa0[3] = __float_as_uint(p0[8 * KPITCH + 4]);
            const float* p1 = p0 + 16 * KPITCH;
            pa1[0] = __float_as_uint(p1[0]);
            pa1[1] = __float_as_uint(p1[8 * KPITCH]);
            pa1[2] = __float_as_uint(p1[4]);
            pa1[3] = __float_as_uint(p1[8 * KPITCH + 4]);
#pragma unroll
            for (int nf = 0; nf < 8; nf++) {
                const float* vr = Vs + (kf * 8 + e) * VPITCH + nf * 8 + g;
                uint32_t b0 = __float_as_uint(vr[0]);
                uint32_t b1 = __float_as_uint(vr[4 * VPITCH]);
                mma_tf32(dpv[0][nf], pa0, b0, b1);
                mma_tf32(dpv[1][nf], pa1, b0, b1);
            }
        }

        if (it < 31) CP_WAIT0();
        __syncthreads();
    }

    // reduce l across quad, normalize, store
#pragma unroll
    for (int r = 0; r < 4; r++) {
        l[r] += __shfl_xor_sync(0xffffffffu, l[r], 1);
        l[r] += __shfl_xor_sync(0xffffffffu, l[r], 2);
    }
#pragma unroll
    for (int r = 0; r < 4; r++) {
        float invl = 1.0f / l[r];
        int row = qbw + (r >> 1) * 16 + (r & 1) * 8 + g;
        float* op = out + ((size_t)(b * SQ + row)) * HD + 2 * e;
#pragma unroll
        for (int nf = 0; nf < 8; nf++) {
            float2 t;
            t.x = dpv[r >> 1][nf][(r & 1) * 2 + 0] * invl;
            t.y = dpv[r >> 1][nf][(r & 1) * 2 + 1] * invl;
            *(float2*)(op + nf * 8) = t;
        }
    }
}

// ===========================================================================
extern "C" void kernel_launch(void* const* d_in, const int* in_sizes, int n_in,
                              void* d_out, int out_size) {
    const float4* q = (const float4*)d_in[0];
    const float4* k = (const float4*)d_in[1];
    const float4* v = (const float4*)d_in[2];
    const int* mask = (const int*)d_in[3];
    float* out = (float*)d_out;

    cudaFuncSetAttribute(flash_fused_kernel,
                         cudaFuncAttributeMaxDynamicSharedMemorySize, SMEM_BYTES);

    round_kernel<<<NELEM / 4 / 256, 256>>>(q, k, v);
    pack_mask_kernel<<<1024, 256>>>(mask);
    flash_fused_kernel<<<NB * (SQ / 128), 256, SMEM_BYTES>>>(out);
}

// round 11
// speedup vs baseline: 2.0733x; 2.0676x over previous
#include <cuda_runtime.h>
#include <cuda_fp16.h>
#include <cstdint>

#define SQ 2048
#define NB 16
#define HD 64
#define MASKW (SQ*SQ/32)        /* 131,072 words */
#define KEEPW (NB*SQ*SQ/32)     /* 2,097,152 words = 8 MB */
#define NELEM (NB*SQ*HD)        /* 2,097,152 per tensor */

__device__ uint32_t g_mbits[MASKW];
__device__ uint32_t g_keep[KEEPW];
__device__ __half g_qh[NELEM];  /* q/8 fp16, [b*SQ+row][d]  */
__device__ __half g_kh[NELEM];  /* k fp16,   [b*SQ+key][d]  */
__device__ __half g_vt[NELEM];  /* v fp16 transposed: [b][d][key] */

// threefry2x32 partitionable, key=(0,42): keep decision for counter i.
// (bits>>9) < 7549747  <=>  bits < 0xE6666600
__device__ __forceinline__ bool tf_keep(uint32_t i) {
    const uint32_t ks1 = 42u;
    const uint32_t ks2 = 0x1BD11BDAu ^ 42u;
    uint32_t x0 = 0u, x1 = i + ks1;
#define TFR(r) { x0 += x1; x1 = __funnelshift_l(x1, x1, r); x1 ^= x0; }
    TFR(13) TFR(15) TFR(26) TFR(6)
    x0 += ks1; x1 += ks2 + 1u;
    TFR(17) TFR(29) TFR(16) TFR(24)
    x0 += ks2; x1 += 2u;
    TFR(13) TFR(15) TFR(26) TFR(6)
    x1 += ks1 + 3u;
    TFR(17) TFR(29) TFR(16) TFR(24)
    x0 += ks1; x1 += ks2 + 4u;
    TFR(13) TFR(15) TFR(26) TFR(6)
    x0 += ks2; x1 += 5u;
#undef TFR
    return (x0 ^ x1) < 0xE6666600u;
}

// ===========================================================================
// gen_keep: full keep bitset, ILP-4
// ===========================================================================
__global__ void gen_keep_kernel() {
    uint32_t lane = threadIdx.x & 31u;
    uint32_t warp = (blockIdx.x * blockDim.x + threadIdx.x) >> 5;
    uint32_t nw   = (gridDim.x * blockDim.x) >> 5;
    for (uint32_t w = warp * 4u; w < KEEPW; w += nw * 4u) {
        uint32_t i0 = w * 32u + lane;
        bool c0 = tf_keep(i0);
        bool c1 = tf_keep(i0 + 32u);
        bool c2 = tf_keep(i0 + 64u);
        bool c3 = tf_keep(i0 + 96u);
        uint4 b;
        b.x = __ballot_sync(0xffffffffu, c0);
        b.y = __ballot_sync(0xffffffffu, c1);
        b.z = __ballot_sync(0xffffffffu, c2);
        b.w = __ballot_sync(0xffffffffu, c3);
        if (lane == 0) *(uint4*)(g_keep + w) = b;
    }
}

// ===========================================================================
// convert q (scaled 1/8) and k to fp16
// ===========================================================================
__global__ void round_qk_kernel(const float4* __restrict__ q,
                                const float4* __restrict__ k) {
    int i = blockIdx.x * blockDim.x + threadIdx.x;   // 0..NELEM/4-1
    float4 t = __ldg(q + i);
    __half2 h0 = __floats2half2_rn(t.x * 0.125f, t.y * 0.125f);
    __half2 h1 = __floats2half2_rn(t.z * 0.125f, t.w * 0.125f);
    uint32_t* qd = (uint32_t*)g_qh + i * 2;
    qd[0] = *(uint32_t*)&h0;
    qd[1] = *(uint32_t*)&h1;
    t = __ldg(k + i);
    h0 = __floats2half2_rn(t.x, t.y);
    h1 = __floats2half2_rn(t.z, t.w);
    uint32_t* kd = (uint32_t*)g_kh + i * 2;
    kd[0] = *(uint32_t*)&h0;
    kd[1] = *(uint32_t*)&h1;
}

// ===========================================================================
// transpose v to fp16 g_vt[b][d][key] (tiled through smem)
// grid = NB*32 blocks (64-key tiles), 256 threads
// ===========================================================================
__global__ void vt_kernel(const float* __restrict__ v) {
    __shared__ __half s[64][65];
    const int b  = blockIdx.x >> 5;
    const int kt = blockIdx.x & 31;
    const int t  = threadIdx.x;
    {
        const int key = t >> 2;
        const int c   = (t & 3) * 16;
        const float4* src = (const float4*)(v + ((size_t)(b * SQ + kt * 64 + key)) * HD + c);
#pragma unroll
        for (int j = 0; j < 4; j++) {
            float4 f = __ldg(src + j);
            s[key][c + j * 4 + 0] = __float2half_rn(f.x);
            s[key][c + j * 4 + 1] = __float2half_rn(f.y);
            s[key][c + j * 4 + 2] = __float2half_rn(f.z);
            s[key][c + j * 4 + 3] = __float2half_rn(f.w);
        }
    }
    __syncthreads();
    {
        const int d  = t >> 2;
        const int kc = (t & 3) * 16;
        uint32_t* dst = (uint32_t*)g_vt + ((((size_t)(b * 64 + d)) * SQ + kt * 64 + kc) >> 1);
#pragma unroll
        for (int j = 0; j < 8; j++) {
            __half2 h = __halves2half2(s[kc + 2 * j][d], s[kc + 2 * j + 1][d]);
            dst[j] = *(uint32_t*)&h;
        }
    }
}

// ===========================================================================
// pack attn_mask into bits (bit=1 -> unmasked)
// ===========================================================================
__global__ void pack_mask_kernel(const int* __restrict__ mask) {
    uint32_t lane = threadIdx.x & 31u;
    uint32_t warp = (blockIdx.x * blockDim.x + threadIdx.x) >> 5;
    uint32_t nw   = (gridDim.x * blockDim.x) >> 5;
    for (uint32_t w = warp * 4u; w < MASKW; w += nw * 4u) {
        int v0 = __ldg(mask + (size_t)w * 32 + lane);
        int v1 = __ldg(mask + (size_t)(w + 1) * 32 + lane);
        int v2 = __ldg(mask + (size_t)(w + 2) * 32 + lane);
        int v3 = __ldg(mask + (size_t)(w + 3) * 32 + lane);
        uint4 b;
        b.x = __ballot_sync(0xffffffffu, v0 != 0);
        b.y = __ballot_sync(0xffffffffu, v1 != 0);
        b.z = __ballot_sync(0xffffffffu, v2 != 0);
        b.w = __ballot_sync(0xffffffffu, v3 != 0);
        if (lane == 0) *(uint4*)(g_mbits + w) = b;
    }
}

// ===========================================================================
// fp16 m16n8k16 flash attention. CTA: 128 q-rows, 4 warps x 32 rows,
// key tile 64, cp.async double-buffered. P stays in registers (QK D-frag
// == PV A-frag layout). K and Vt smem pitch 36 words (== 4 mod 32:
// conflict-free fragment reads).
// ===========================================================================

#define KP32 36                          /* 32-bit words per smem row */
#define KROWB (KP32*4)                   /* 144 B */
#define KTILEB (64*KROWB)                /* 9216 B */
#define BUFB (2*KTILEB)                  /* K + Vt = 18432 B */
#define SMEM_BYTES (2*BUFB)              /* 36864 B, double buffered */

#define CP16(dst, src) asm volatile("cp.async.cg.shared.global [%0], [%1], 16;" :: "r"(dst), "l"(src) : "memory")
#define CP_COMMIT()    asm volatile("cp.async.commit_group;" ::: "memory")
#define CP_WAIT0()     asm volatile("cp.async.wait_group 0;" ::: "memory")

__device__ __forceinline__ uint32_t s2u(const void* p) {
    uint32_t a;
    asm("{ .reg .u64 t; cvta.to.shared.u64 t, %1; cvt.u32.u64 %0, t; }" : "=r"(a) : "l"(p));
    return a;
}

__device__ __forceinline__ void mma_f16(float c[4], const uint32_t a[4],
                                        uint32_t b0, uint32_t b1) {
    asm volatile(
        "mma.sync.aligned.m16n8k16.row.col.f32.f16.f16.f32 "
        "{%0,%1,%2,%3}, {%4,%5,%6,%7}, {%8,%9}, {%0,%1,%2,%3};"
        : "+f"(c[0]), "+f"(c[1]), "+f"(c[2]), "+f"(c[3])
        : "r"(a[0]), "r"(a[1]), "r"(a[2]), "r"(a[3]), "r"(b0), "r"(b1));
}

__global__ void __launch_bounds__(128, 2) flash_mma_kernel(float* __restrict__ out)
{
    extern __shared__ char smem[];
    const uint32_t sb = s2u(smem);

    const int tid  = threadIdx.x;
    const int wid  = tid >> 5;
    const int lane = tid & 31;
    const int g    = lane >> 2;
    const int e    = lane & 3;
    const int b    = blockIdx.x >> 4;
    const int qt   = blockIdx.x & 15;
    const int qbw  = qt * 128 + wid * 32;
    const float INVK = (float)(1.0 / 0.9);

    // staging role: 2 threads per row (64 rows), 64B (4 chunks) each
    const int srow = tid >> 1;
    const int shf  = tid & 1;
    const __half* ksrc = g_kh + ((size_t)(b * SQ + srow)) * HD + shf * 32;
    const __half* vsrc = g_vt + ((size_t)(b * 64 + srow)) * SQ + shf * 32;
    const uint32_t kdst = sb + (uint32_t)(srow * KROWB + shf * 64);
    const uint32_t vdst = kdst + KTILEB;

    // ---- Q fragments (fp16), persistent: qa[mf][kb][4] ----
    uint32_t qa[2][4][4];
#pragma unroll
    for (int mf = 0; mf < 2; mf++) {
        const uint32_t* q0 = (const uint32_t*)g_qh + ((size_t)(b * SQ + qbw + mf * 16 + g)) * 32;
        const uint32_t* q1 = q0 + 8 * 32;
#pragma unroll
        for (int kb = 0; kb < 4; kb++) {
            qa[mf][kb][0] = __ldg(q0 + kb * 8 + e);
            qa[mf][kb][1] = __ldg(q1 + kb * 8 + e);
            qa[mf][kb][2] = __ldg(q0 + kb * 8 + e + 4);
            qa[mf][kb][3] = __ldg(q1 + kb * 8 + e + 4);
        }
    }

    float dpv[2][8][4];
#pragma unroll
    for (int mf = 0; mf < 2; mf++)
#pragma unroll
        for (int nf = 0; nf < 8; nf++)
#pragma unroll
            for (int j = 0; j < 4; j++) dpv[mf][nf][j] = 0.0f;
    float l[4] = {0.f, 0.f, 0.f, 0.f};

    // ---- stage tile 0 ----
#pragma unroll
    for (int c = 0; c < 4; c++) {
        CP16(kdst + c * 16, (const char*)ksrc + c * 16);
        CP16(vdst + c * 16, (const char*)vsrc + c * 16);
    }
    CP_COMMIT(); CP_WAIT0();
    __syncthreads();

    for (int it = 0; it < 32; it++) {
        const int cur = it & 1;
        const uint32_t* Ksw = (const uint32_t*)(smem + cur * BUFB);
        const uint32_t* Vtw = Ksw + KTILEB / 4;

        // ---- stage next tile ----
        if (it < 31) {
            const uint32_t boff = (uint32_t)((cur ^ 1) * BUFB);
            const char* kn = (const char*)(ksrc + (size_t)(it + 1) * 64 * HD);
            const char* vn = (const char*)(vsrc + (it + 1) * 64);
#pragma unroll
            for (int c = 0; c < 4; c++) {
                CP16(kdst + boff + c * 16, kn + c * 16);
                CP16(vdst + boff + c * 16, vn + c * 16);
            }
            CP_COMMIT();
        }

        // mask + keep words for my 4 rows
        uint2 mwv[4], kwv[4];
#pragma unroll
        for (int r = 0; r < 4; r++) {
            int row = qbw + (r >> 1) * 16 + (r & 1) * 8 + g;
            mwv[r] = *(const uint2*)(g_mbits + (size_t)row * (SQ / 32) + it * 2);
            kwv[r] = *(const uint2*)(g_keep + ((size_t)(b * SQ + row)) * (SQ / 32) + it * 2);
        }

        // ---- QK^T + epilogue -> P fragments in registers ----
        uint32_t pa[2][4][4];
#pragma unroll
        for (int np = 0; np < 4; np++) {
            float c[2][2][4];                    // [s][mf][4]
#pragma unroll
            for (int s = 0; s < 2; s++)
#pragma unroll
                for (int mf = 0; mf < 2; mf++)
#pragma unroll
                    for (int j = 0; j < 4; j++) c[s][mf][j] = 0.0f;
#pragma unroll
            for (int kb = 0; kb < 4; kb++) {
                const uint32_t* kr0 = Ksw + ((np * 2 + 0) * 8 + g) * KP32 + kb * 8 + e;
                const uint32_t* kr1 = Ksw + ((np * 2 + 1) * 8 + g) * KP32 + kb * 8 + e;
                uint32_t b00 = kr0[0], b01 = kr0[4];
                uint32_t b10 = kr1[0], b11 = kr1[4];
                mma_f16(c[0][0], qa[0][kb], b00, b01);
                mma_f16(c[0][1], qa[1][kb], b00, b01);
                mma_f16(c[1][0], qa[0][kb], b10, b11);
                mma_f16(c[1][1], qa[1][kb], b10, b11);
            }
#pragma unroll
            for (int s = 0; s < 2; s++) {
                const int nf = np * 2 + s;
                const int bit = (nf & 3) * 8 + 2 * e;
#pragma unroll
                for (int mf = 0; mf < 2; mf++) {
#pragma unroll
                    for (int hf = 0; hf < 2; hf++) {
                        const int r = mf * 2 + hf;
                        uint32_t mword = (nf < 4) ? mwv[r].x : mwv[r].y;
                        uint32_t kword = (nf < 4) ? kwv[r].x : kwv[r].y;
                        float s0 = c[s][mf][hf * 2 + 0];
                        float s1 = c[s][mf][hf * 2 + 1];
                        float p0 = ((mword >> bit) & 1u) ? __expf(s0) : 0.0f;
                        float p1 = ((mword >> (bit + 1)) & 1u) ? __expf(s1) : 0.0f;
                        l[r] += p0 + p1;
                        float d0 = ((kword >> bit) & 1u) ? p0 * INVK : 0.0f;
                        float d1 = ((kword >> (bit + 1)) & 1u) ? p1 * INVK : 0.0f;
                        __half2 h = __floats2half2_rn(d0, d1);
                        pa[mf][np][(s << 1) | hf] = *(uint32_t*)&h;
                    }
                }
            }
        }

        // ---- D_pv += P . V  (P already fragment-shaped) ----
#pragma unroll
        for (int kb = 0; kb < 4; kb++) {
#pragma unroll
            for (int nf2 = 0; nf2 < 8; nf2++) {
                const uint32_t* vr = Vtw + (nf2 * 8 + g) * KP32 + kb * 8 + e;
                uint32_t b0 = vr[0], b1 = vr[4];
                mma_f16(dpv[0][nf2], pa[0][kb], b0, b1);
                mma_f16(dpv[1][nf2], pa[1][kb], b0, b1);
            }
        }

        if (it < 31) CP_WAIT0();
        __syncthreads();
    }

    // reduce l across quad, normalize, store
#pragma unroll
    for (int r = 0; r < 4; r++) {
        l[r] += __shfl_xor_sync(0xffffffffu, l[r], 1);
        l[r] += __shfl_xor_sync(0xffffffffu, l[r], 2);
    }
#pragma unroll
    for (int r = 0; r < 4; r++) {
        float invl = 1.0f / l[r];
        int row = qbw + (r >> 1) * 16 + (r & 1) * 8 + g;
        float* op = out + ((size_t)(b * SQ + row)) * HD + 2 * e;
#pragma unroll
        for (int nf2 = 0; nf2 < 8; nf2++) {
            float2 t;
            t.x = dpv[r >> 1][nf2][(r & 1) * 2 + 0] * invl;
            t.y = dpv[r >> 1][nf2][(r & 1) * 2 + 1] * invl;
            *(float2*)(op + nf2 * 8) = t;
        }
    }
}

// ===========================================================================
extern "C" void kernel_launch(void* const* d_in, const int* in_sizes, int n_in,
                              void* d_out, int out_size) {
    const float* q = (const float*)d_in[0];
    const float* k = (const float*)d_in[1];
    const float* v = (const float*)d_in[2];
    const int* mask = (const int*)d_in[3];
    float* out = (float*)d_out;

    round_qk_kernel<<<NELEM / 4 / 256, 256>>>((const float4*)q, (const float4*)k);
    vt_kernel<<<NB * 32, 256>>>(v);
    pack_mask_kernel<<<1024, 256>>>(mask);
    gen_keep_kernel<<<2048, 256>>>();
    flash_mma_kernel<<<NB * (SQ / 128), 128, SMEM_BYTES>>>(out);
}